// round 4
// baseline (speedup 1.0000x reference)
#include <cuda_runtime.h>
#include <cuda_bf16.h>
#include <cstdint>

// Problem constants
#define B_WIN 256
#define NTOK  144
#define DIM   384
#define HEADS 12
#define HD    32
#define QKV_N 1152
#define MROWS (B_WIN*NTOK)        // 36864
#define QSCALE 0.17677669529663689f   // 32^-0.5

// ---------------- Scratch (static device globals; allocation-free) ----------
__device__ float g_q[14155776];   // (b*12+h, i, d)
__device__ float g_k[14155776];
__device__ float g_v[14155776];
__device__ __nv_bfloat16 g_xa_hi[14155776];   // x split, [36864][384]
__device__ __nv_bfloat16 g_xa_lo[14155776];
__device__ __nv_bfloat16 g_wqkvT_hi[442368];  // [1152][384]
__device__ __nv_bfloat16 g_wqkvT_lo[442368];
__device__ __nv_bfloat16 g_woutT_hi[147456];  // [384][384]
__device__ __nv_bfloat16 g_woutT_lo[147456];
__device__ __nv_bfloat16 g_att_hi[14155776];  // attention out split, [36864][384]
__device__ __nv_bfloat16 g_att_lo[14155776];

// ---------------- helpers ---------------------------------------------------
__device__ __forceinline__ uint32_t smem_u32(const void* p) {
    return (uint32_t)__cvta_generic_to_shared(p);
}
__device__ __forceinline__ uint32_t pack_bf2(__nv_bfloat16 a, __nv_bfloat16 b) {
    return (uint32_t)__bfloat16_as_ushort(a) | ((uint32_t)__bfloat16_as_ushort(b) << 16);
}
__device__ __forceinline__ void ldsm_x4(uint32_t* r, uint32_t addr) {
    asm volatile("ldmatrix.sync.aligned.m8n8.x4.shared.b16 {%0,%1,%2,%3}, [%4];"
                 : "=r"(r[0]), "=r"(r[1]), "=r"(r[2]), "=r"(r[3]) : "r"(addr));
}
__device__ __forceinline__ void mma_bf16(float* c, const uint32_t* a, const uint32_t* b) {
    asm volatile(
        "mma.sync.aligned.m16n8k16.row.col.f32.bf16.bf16.f32 "
        "{%0,%1,%2,%3}, {%4,%5,%6,%7}, {%8,%9}, {%0,%1,%2,%3};"
        : "+f"(c[0]), "+f"(c[1]), "+f"(c[2]), "+f"(c[3])
        : "r"(a[0]), "r"(a[1]), "r"(a[2]), "r"(a[3]), "r"(b[0]), "r"(b[1]));
}

// ---------------------------------------------------------------------------
// Prep: split x (fp32) into bf16 hi/lo
// ---------------------------------------------------------------------------
__global__ void convert_x_kernel(const float* __restrict__ x,
                                 __nv_bfloat16* __restrict__ hi,
                                 __nv_bfloat16* __restrict__ lo, int n4)
{
    int idx = blockIdx.x * blockDim.x + threadIdx.x;
    int stride = gridDim.x * blockDim.x;
    for (; idx < n4; idx += stride) {
        float4 v = ((const float4*)x)[idx];
        __nv_bfloat16 h0 = __float2bfloat16(v.x);
        __nv_bfloat16 h1 = __float2bfloat16(v.y);
        __nv_bfloat16 h2 = __float2bfloat16(v.z);
        __nv_bfloat16 h3 = __float2bfloat16(v.w);
        __nv_bfloat16 l0 = __float2bfloat16(v.x - __bfloat162float(h0));
        __nv_bfloat16 l1 = __float2bfloat16(v.y - __bfloat162float(h1));
        __nv_bfloat16 l2 = __float2bfloat16(v.z - __bfloat162float(h2));
        __nv_bfloat16 l3 = __float2bfloat16(v.w - __bfloat162float(h3));
        ((uint2*)hi)[idx] = make_uint2(pack_bf2(h0, h1), pack_bf2(h2, h3));
        ((uint2*)lo)[idx] = make_uint2(pack_bf2(l0, l1), pack_bf2(l2, l3));
    }
}

// Prep: transpose + split weight w[K][Nn] -> wT[Nn][K] bf16 hi/lo
__global__ void convert_wT_kernel(const float* __restrict__ w,
                                  __nv_bfloat16* __restrict__ hi,
                                  __nv_bfloat16* __restrict__ lo,
                                  int K, int Nn)
{
    int idx = blockIdx.x * blockDim.x + threadIdx.x;
    int total = K * Nn;
    if (idx >= total) return;
    int n = idx / K, k = idx - n * K;
    float v = w[(size_t)k * Nn + n];
    __nv_bfloat16 h = __float2bfloat16(v);
    __nv_bfloat16 l = __float2bfloat16(v - __bfloat162float(h));
    hi[idx] = h;
    lo[idx] = l;
}

// ---------------------------------------------------------------------------
// HMMA split-bf16 GEMM: D(128x128) = A(128x384) @ B^T(128x384), fp32 accum
// BM=BN=128, BK=64; 8 warps as 2(m) x 4(n); warp tile 64x32.
// smem: 4 tiles (Ah, Al, Bh, Bl), each 128 rows x 64 bf16 (128B), XOR-swizzled.
// mode 0: qkv epilogue (scatter to g_q/g_k/g_v + bias + q-scale)
// mode 1: out epilogue (bias, write to out)
// ---------------------------------------------------------------------------
#define TILE_B 16384   // bytes per tile

__global__ __launch_bounds__(256, 2)
void hmma_gemm_kernel(const __nv_bfloat16* __restrict__ Ah,
                      const __nv_bfloat16* __restrict__ Al,
                      const __nv_bfloat16* __restrict__ Bh,
                      const __nv_bfloat16* __restrict__ Bl,
                      const float* __restrict__ bias,
                      float* __restrict__ outp, int mode, int kchunks)
{
    extern __shared__ char smem[];
    char* sAh = smem;
    char* sAl = smem + TILE_B;
    char* sBh = smem + 2 * TILE_B;
    char* sBl = smem + 3 * TILE_B;
    const uint32_t uAh = smem_u32(sAh), uAl = smem_u32(sAl);
    const uint32_t uBh = smem_u32(sBh), uBl = smem_u32(sBl);

    const int tid = threadIdx.x;
    const int wid = tid >> 5, lane = tid & 31;
    const int bm = blockIdx.y * 128;
    const int bn = blockIdx.x * 128;
    const int wm = wid >> 2, wn = wid & 3;
    const int m0w = wm * 64, n0w = wn * 32;

    float acc[4][4][4];
#pragma unroll
    for (int mt = 0; mt < 4; mt++)
#pragma unroll
        for (int nt = 0; nt < 4; nt++)
#pragma unroll
            for (int e = 0; e < 4; e++) acc[mt][nt][e] = 0.f;

    const int lr = lane & 15;          // ldmatrix row within 16
    const int lc = lane >> 4;          // ldmatrix col half (0/1)

    for (int kc = 0; kc < kchunks; kc++) {
        // ---- fill tiles ----
#pragma unroll
        for (int it = 0; it < 4; it++) {
            int v = tid + it * 256;        // 0..1023
            int r = v >> 3, c = v & 7;
            size_t gA = (size_t)(bm + r) * 384 + kc * 64 + c * 8;
            size_t gB = (size_t)(bn + r) * 384 + kc * 64 + c * 8;
            uint32_t d = r * 128 + ((c ^ (r & 7)) * 16);
            *(uint4*)(sAh + d) = *(const uint4*)(Ah + gA);
            *(uint4*)(sAl + d) = *(const uint4*)(Al + gA);
            *(uint4*)(sBh + d) = *(const uint4*)(Bh + gB);
            *(uint4*)(sBl + d) = *(const uint4*)(Bl + gB);
        }
        __syncthreads();

#pragma unroll
        for (int k16 = 0; k16 < 4; k16++) {
            const int chunk = k16 * 2 + lc;
            uint32_t aH[4][4], aL[4][4];
            uint32_t bH[4][2], bL[4][2];
            // A frags (hi, lo): 4 m-tiles
#pragma unroll
            for (int mt = 0; mt < 4; mt++) {
                int r = m0w + mt * 16 + lr;
                uint32_t off = r * 128 + ((chunk ^ (r & 7)) * 16);
                ldsm_x4(aH[mt], uAh + off);
                ldsm_x4(aL[mt], uAl + off);
            }
            // B frags (hi, lo): 2 x4 loads cover 4 n-tiles
#pragma unroll
            for (int np = 0; np < 2; np++) {
                int r = n0w + np * 16 + lr;
                uint32_t off = r * 128 + ((chunk ^ (r & 7)) * 16);
                uint32_t t[4];
                ldsm_x4(t, uBh + off);
                bH[2 * np][0] = t[0]; bH[2 * np][1] = t[2];
                bH[2 * np + 1][0] = t[1]; bH[2 * np + 1][1] = t[3];
                ldsm_x4(t, uBl + off);
                bL[2 * np][0] = t[0]; bL[2 * np][1] = t[2];
                bL[2 * np + 1][0] = t[1]; bL[2 * np + 1][1] = t[3];
            }
            // 3 combos: AhBh, AhBl, AlBh
#pragma unroll
            for (int mt = 0; mt < 4; mt++)
#pragma unroll
                for (int nt = 0; nt < 4; nt++) {
                    mma_bf16(acc[mt][nt], aH[mt], bH[nt]);
                    mma_bf16(acc[mt][nt], aH[mt], bL[nt]);
                    mma_bf16(acc[mt][nt], aL[mt], bH[nt]);
                }
        }
        __syncthreads();
    }

    // ---- epilogue (direct from fragments) ----
    if (mode == 0) {
#pragma unroll
        for (int mt = 0; mt < 4; mt++) {
#pragma unroll
            for (int nt = 0; nt < 4; nt++) {
                int col = bn + n0w + nt * 8 + (lane & 3) * 2;
                int s = col / 384;
                int rem = col - s * 384;
                int h = rem >> 5, d = rem & 31;
                float* dst = (s == 0) ? g_q : (s == 1 ? g_k : g_v);
                float sc = (s == 0) ? QSCALE : 1.0f;
                float b0 = bias[col], b1 = bias[col + 1];
#pragma unroll
                for (int half = 0; half < 2; half++) {
                    int row = bm + m0w + mt * 16 + (lane >> 2) + half * 8;
                    int b = row / 144, i = row - b * 144;
                    float2 v;
                    v.x = (acc[mt][nt][half * 2 + 0] + b0) * sc;
                    v.y = (acc[mt][nt][half * 2 + 1] + b1) * sc;
                    *(float2*)(dst + (((size_t)b * 12 + h) * 144 + i) * 32 + d) = v;
                }
            }
        }
    } else {
#pragma unroll
        for (int mt = 0; mt < 4; mt++) {
#pragma unroll
            for (int nt = 0; nt < 4; nt++) {
                int col = bn + n0w + nt * 8 + (lane & 3) * 2;
                float b0 = bias[col], b1 = bias[col + 1];
#pragma unroll
                for (int half = 0; half < 2; half++) {
                    int row = bm + m0w + mt * 16 + (lane >> 2) + half * 8;
                    float2 v;
                    v.x = acc[mt][nt][half * 2 + 0] + b0;
                    v.y = acc[mt][nt][half * 2 + 1] + b1;
                    *(float2*)(outp + (size_t)row * 384 + col) = v;
                }
            }
        }
    }
}

// ---------------------------------------------------------------------------
// Fused attention per (b,h); output split bf16 hi/lo for the out-projection
// ---------------------------------------------------------------------------
#define SS_LD 148

__global__ __launch_bounds__(512, 1)
void attn_kernel(const float* __restrict__ mask,
                 const float* __restrict__ bias_table,
                 const int*   __restrict__ pos_idx)
{
    extern __shared__ float sm[];
    float* sQt = sm;                  // [32][144]
    float* sKt = sQt + 32 * 144;      // [32][144]
    float* sV  = sKt + 32 * 144;      // [144][32]
    float* sS  = sV  + 144 * 32;      // [144][SS_LD]
    float* sB  = sS  + 144 * SS_LD;   // [2592]

    const int bh = blockIdx.x;
    const int b = bh / HEADS, h = bh - b * HEADS;
    const int g  = b >> 5;
    const int t  = b & 31;
    const int mw = b & 7;

    const int tid = threadIdx.x;
    const int wid = tid >> 5, lane = tid & 31;

    const float* qb = g_q + (size_t)bh * (NTOK * HD);
    const float* kb = g_k + (size_t)bh * (NTOK * HD);
    const float* vb = g_v + (size_t)bh * (NTOK * HD);

    for (int idx = tid; idx < NTOK * 8; idx += 512) {
        int i = idx >> 3;
        int d0 = (idx & 7) * 4;
        float4 qv = *(const float4*)(qb + i * HD + d0);
        float4 kv = *(const float4*)(kb + i * HD + d0);
        float4 vv = *(const float4*)(vb + i * HD + d0);
        sQt[(d0 + 0) * 144 + i] = qv.x; sQt[(d0 + 1) * 144 + i] = qv.y;
        sQt[(d0 + 2) * 144 + i] = qv.z; sQt[(d0 + 3) * 144 + i] = qv.w;
        sKt[(d0 + 0) * 144 + i] = kv.x; sKt[(d0 + 1) * 144 + i] = kv.y;
        sKt[(d0 + 2) * 144 + i] = kv.z; sKt[(d0 + 3) * 144 + i] = kv.w;
        *(float4*)(sV + i * HD + d0) = vv;
    }
    for (int s = tid; s < 2592; s += 512)
        sB[s] = bias_table[(size_t)pos_idx[8 * s + g] * (32 * HEADS) + t * HEADS + h];
    __syncthreads();

    const int li = lane & 3;
    const int lj = lane >> 2;
    for (int p = wid; p < 45; p += 16) {
        int pi = p / 5, pj = p - pi * 5;
        int ti = pi * 4 + li;
        int tj = pj * 8 + lj;
        if (tj >= 36) continue;
        int i0 = ti * 4, j0 = tj * 4;
        float acc[4][4];
#pragma unroll
        for (int r = 0; r < 4; r++)
#pragma unroll
            for (int c = 0; c < 4; c++) acc[r][c] = 0.f;
#pragma unroll
        for (int d = 0; d < HD; d++) {
            float4 qv = *(const float4*)(sQt + d * 144 + i0);
            float4 kv = *(const float4*)(sKt + d * 144 + j0);
            float qa[4] = {qv.x, qv.y, qv.z, qv.w};
            float ka[4] = {kv.x, kv.y, kv.z, kv.w};
#pragma unroll
            for (int r = 0; r < 4; r++)
#pragma unroll
                for (int c = 0; c < 4; c++) acc[r][c] += qa[r] * ka[c];
        }
#pragma unroll
        for (int r = 0; r < 4; r++) {
            int i = i0 + r;
            int im = i % 18;
            float4 mv = *(const float4*)(mask + ((size_t)mw * 144 + i) * 144 + j0);
            float4 bv = *(const float4*)(sB + im * 144 + j0);
            float4 sv;
            sv.x = acc[r][0] + bv.x + mv.x;
            sv.y = acc[r][1] + bv.y + mv.y;
            sv.z = acc[r][2] + bv.z + mv.z;
            sv.w = acc[r][3] + bv.w + mv.w;
            *(float4*)(sS + i * SS_LD + j0) = sv;
        }
    }
    __syncthreads();

    for (int i = wid; i < NTOK; i += 16) {
        float* row = sS + i * SS_LD;
        float m = -1e30f;
        for (int j = lane; j < NTOK; j += 32) m = fmaxf(m, row[j]);
#pragma unroll
        for (int o = 16; o > 0; o >>= 1) m = fmaxf(m, __shfl_xor_sync(0xffffffffu, m, o));
        float sum = 0.f;
        for (int j = lane; j < NTOK; j += 32) {
            float e = __expf(row[j] - m);
            row[j] = e;
            sum += e;
        }
#pragma unroll
        for (int o = 16; o > 0; o >>= 1) sum += __shfl_xor_sync(0xffffffffu, sum, o);
        float inv = 1.f / sum;
        for (int j = lane; j < NTOK; j += 32) row[j] *= inv;
    }
    __syncthreads();

    if (tid < 288) {
        int ti = tid >> 3, dq = tid & 7;
        int i0 = ti * 4, d0 = dq * 4;
        float acc[4][4];
#pragma unroll
        for (int r = 0; r < 4; r++)
#pragma unroll
            for (int c = 0; c < 4; c++) acc[r][c] = 0.f;
        for (int j0 = 0; j0 < NTOK; j0 += 4) {
            float pf[4][4];
#pragma unroll
            for (int r = 0; r < 4; r++) {
                float4 pv = *(const float4*)(sS + (i0 + r) * SS_LD + j0);
                pf[r][0] = pv.x; pf[r][1] = pv.y; pf[r][2] = pv.z; pf[r][3] = pv.w;
            }
#pragma unroll
            for (int jj = 0; jj < 4; jj++) {
                float4 vv = *(const float4*)(sV + (j0 + jj) * HD + d0);
                float vf[4] = {vv.x, vv.y, vv.z, vv.w};
#pragma unroll
                for (int r = 0; r < 4; r++)
#pragma unroll
                    for (int c = 0; c < 4; c++) acc[r][c] += pf[r][jj] * vf[c];
            }
        }
#pragma unroll
        for (int r = 0; r < 4; r++) {
            size_t base = ((size_t)b * NTOK + i0 + r) * DIM + h * HD + d0;
            __nv_bfloat16 h0 = __float2bfloat16(acc[r][0]);
            __nv_bfloat16 h1 = __float2bfloat16(acc[r][1]);
            __nv_bfloat16 h2 = __float2bfloat16(acc[r][2]);
            __nv_bfloat16 h3 = __float2bfloat16(acc[r][3]);
            __nv_bfloat16 l0 = __float2bfloat16(acc[r][0] - __bfloat162float(h0));
            __nv_bfloat16 l1 = __float2bfloat16(acc[r][1] - __bfloat162float(h1));
            __nv_bfloat16 l2 = __float2bfloat16(acc[r][2] - __bfloat162float(h2));
            __nv_bfloat16 l3 = __float2bfloat16(acc[r][3] - __bfloat162float(h3));
            *(uint2*)(g_att_hi + base) = make_uint2(pack_bf2(h0, h1), pack_bf2(h2, h3));
            *(uint2*)(g_att_lo + base) = make_uint2(pack_bf2(l0, l1), pack_bf2(l2, l3));
        }
    }
}

// ---------------------------------------------------------------------------
extern "C" void kernel_launch(void* const* d_in, const int* in_sizes, int n_in,
                              void* d_out, int out_size)
{
    const float* x          = (const float*)d_in[0];
    const float* mask       = (const float*)d_in[1];
    const float* w_qkv      = (const float*)d_in[2];
    const float* b_qkv      = (const float*)d_in[3];
    const float* w_out      = (const float*)d_in[4];
    const float* b_out      = (const float*)d_in[5];
    const float* bias_table = (const float*)d_in[6];
    const int*   pos_idx    = (const int*)d_in[7];
    float* out = (float*)d_out;

    __nv_bfloat16 *xa_hi, *xa_lo, *wqT_hi, *wqT_lo, *woT_hi, *woT_lo;
    __nv_bfloat16 *att_hi, *att_lo;
    cudaGetSymbolAddress((void**)&xa_hi, g_xa_hi);
    cudaGetSymbolAddress((void**)&xa_lo, g_xa_lo);
    cudaGetSymbolAddress((void**)&wqT_hi, g_wqkvT_hi);
    cudaGetSymbolAddress((void**)&wqT_lo, g_wqkvT_lo);
    cudaGetSymbolAddress((void**)&woT_hi, g_woutT_hi);
    cudaGetSymbolAddress((void**)&woT_lo, g_woutT_lo);
    cudaGetSymbolAddress((void**)&att_hi, g_att_hi);
    cudaGetSymbolAddress((void**)&att_lo, g_att_lo);

    const int smem_attn = (32 * 144 * 2 + 144 * 32 + 144 * SS_LD + 2592) * 4;
    cudaFuncSetAttribute(attn_kernel, cudaFuncAttributeMaxDynamicSharedMemorySize,
                         smem_attn);
    const int smem_gemm = 4 * TILE_B;  // 64 KB
    cudaFuncSetAttribute(hmma_gemm_kernel, cudaFuncAttributeMaxDynamicSharedMemorySize,
                         smem_gemm);

    convert_x_kernel<<<2048, 256>>>(x, xa_hi, xa_lo, MROWS * DIM / 4);
    convert_wT_kernel<<<(DIM * QKV_N + 255) / 256, 256>>>(w_qkv, wqT_hi, wqT_lo,
                                                          DIM, QKV_N);
    convert_wT_kernel<<<(DIM * DIM + 255) / 256, 256>>>(w_out, woT_hi, woT_lo,
                                                        DIM, DIM);
    // qkv projection
    hmma_gemm_kernel<<<dim3(QKV_N / 128, MROWS / 128), 256, smem_gemm>>>(
        xa_hi, xa_lo, wqT_hi, wqT_lo, b_qkv, nullptr, 0, 6);
    // attention
    attn_kernel<<<B_WIN * HEADS, 512, smem_attn>>>(mask, bias_table, pos_idx);
    // output projection
    hmma_gemm_kernel<<<dim3(DIM / 128, MROWS / 128), 256, smem_gemm>>>(
        att_hi, att_lo, woT_hi, woT_lo, b_out, out, 1, 6);
}

// round 6
// speedup vs baseline: 2.0809x; 2.0809x over previous
#include <cuda_runtime.h>
#include <cuda_bf16.h>
#include <cstdint>

// Problem constants
#define B_WIN 256
#define NTOK  144
#define DIM   384
#define HEADS 12
#define HD    32
#define QKV_N 1152
#define MROWS (B_WIN*NTOK)        // 36864
#define QSCALE 0.17677669529663689f   // 32^-0.5
#define QKV_PLANE 56623104ll          // 3072*144*128 bytes per q/k/v plane

// ---------------- Scratch (static device globals; allocation-free) ----------
// Packed q/k/v: [3][3072 bh][144 rows][128B]; row = 8 swizzled 16B chunks:
// logical chunks 0-3 = bf16 hi (d 0..31), 4-7 = bf16 lo. phys = l ^ (row&7).
__device__ char g_qkvp[169869312];
__device__ __nv_bfloat16 g_xa_hi[14155776];   // x split, [36864][384]
__device__ __nv_bfloat16 g_xa_lo[14155776];
__device__ __nv_bfloat16 g_wqkvT_hi[442368];  // [1152][384]
__device__ __nv_bfloat16 g_wqkvT_lo[442368];
__device__ __nv_bfloat16 g_woutT_hi[147456];  // [384][384]
__device__ __nv_bfloat16 g_woutT_lo[147456];
__device__ __nv_bfloat16 g_att_hi[14155776];  // attention out split, [36864][384]
__device__ __nv_bfloat16 g_att_lo[14155776];

// ---------------- helpers ---------------------------------------------------
__device__ __forceinline__ uint32_t smem_u32(const void* p) {
    return (uint32_t)__cvta_generic_to_shared(p);
}
__device__ __forceinline__ uint32_t pack_bf2(__nv_bfloat16 a, __nv_bfloat16 b) {
    return (uint32_t)__bfloat16_as_ushort(a) | ((uint32_t)__bfloat16_as_ushort(b) << 16);
}
__device__ __forceinline__ void ldsm_x4(uint32_t* r, uint32_t addr) {
    asm volatile("ldmatrix.sync.aligned.m8n8.x4.shared.b16 {%0,%1,%2,%3}, [%4];"
                 : "=r"(r[0]), "=r"(r[1]), "=r"(r[2]), "=r"(r[3]) : "r"(addr));
}
__device__ __forceinline__ void ldsm_x4_t(uint32_t* r, uint32_t addr) {
    asm volatile("ldmatrix.sync.aligned.m8n8.x4.trans.shared.b16 {%0,%1,%2,%3}, [%4];"
                 : "=r"(r[0]), "=r"(r[1]), "=r"(r[2]), "=r"(r[3]) : "r"(addr));
}
__device__ __forceinline__ void mma_bf16(float* c, const uint32_t* a, const uint32_t* b) {
    asm volatile(
        "mma.sync.aligned.m16n8k16.row.col.f32.bf16.bf16.f32 "
        "{%0,%1,%2,%3}, {%4,%5,%6,%7}, {%8,%9}, {%0,%1,%2,%3};"
        : "+f"(c[0]), "+f"(c[1]), "+f"(c[2]), "+f"(c[3])
        : "r"(a[0]), "r"(a[1]), "r"(a[2]), "r"(a[3]), "r"(b[0]), "r"(b[1]));
}

// ---------------------------------------------------------------------------
// Prep: split x (fp32) into bf16 hi/lo
// ---------------------------------------------------------------------------
__global__ void convert_x_kernel(const float* __restrict__ x,
                                 __nv_bfloat16* __restrict__ hi,
                                 __nv_bfloat16* __restrict__ lo, int n4)
{
    int idx = blockIdx.x * blockDim.x + threadIdx.x;
    int stride = gridDim.x * blockDim.x;
    for (; idx < n4; idx += stride) {
        float4 v = ((const float4*)x)[idx];
        __nv_bfloat16 h0 = __float2bfloat16(v.x);
        __nv_bfloat16 h1 = __float2bfloat16(v.y);
        __nv_bfloat16 h2 = __float2bfloat16(v.z);
        __nv_bfloat16 h3 = __float2bfloat16(v.w);
        __nv_bfloat16 l0 = __float2bfloat16(v.x - __bfloat162float(h0));
        __nv_bfloat16 l1 = __float2bfloat16(v.y - __bfloat162float(h1));
        __nv_bfloat16 l2 = __float2bfloat16(v.z - __bfloat162float(h2));
        __nv_bfloat16 l3 = __float2bfloat16(v.w - __bfloat162float(h3));
        ((uint2*)hi)[idx] = make_uint2(pack_bf2(h0, h1), pack_bf2(h2, h3));
        ((uint2*)lo)[idx] = make_uint2(pack_bf2(l0, l1), pack_bf2(l2, l3));
    }
}

// Prep: transpose + split weight w[K][Nn] -> wT[Nn][K] bf16 hi/lo
__global__ void convert_wT_kernel(const float* __restrict__ w,
                                  __nv_bfloat16* __restrict__ hi,
                                  __nv_bfloat16* __restrict__ lo,
                                  int K, int Nn)
{
    int idx = blockIdx.x * blockDim.x + threadIdx.x;
    int total = K * Nn;
    if (idx >= total) return;
    int n = idx / K, k = idx - n * K;
    float v = w[(size_t)k * Nn + n];
    __nv_bfloat16 h = __float2bfloat16(v);
    __nv_bfloat16 l = __float2bfloat16(v - __bfloat162float(h));
    hi[idx] = h;
    lo[idx] = l;
}

// ---------------------------------------------------------------------------
// HMMA split-bf16 GEMM: D(128x128) = A(128x384) @ B^T(128x384), fp32 accum
// mode 0: qkv epilogue -> packed bf16 hi/lo q/k/v planes (+bias, q-scale)
// mode 1: out epilogue (bias, write fp32 out)
// ---------------------------------------------------------------------------
#define TILE_B 16384

__global__ __launch_bounds__(256, 2)
void hmma_gemm_kernel(const __nv_bfloat16* __restrict__ Ah,
                      const __nv_bfloat16* __restrict__ Al,
                      const __nv_bfloat16* __restrict__ Bh,
                      const __nv_bfloat16* __restrict__ Bl,
                      const float* __restrict__ bias,
                      float* __restrict__ outp, int mode, int kchunks)
{
    extern __shared__ char smem[];
    char* sAh = smem;
    char* sAl = smem + TILE_B;
    char* sBh = smem + 2 * TILE_B;
    char* sBl = smem + 3 * TILE_B;
    const uint32_t uAh = smem_u32(sAh), uAl = smem_u32(sAl);
    const uint32_t uBh = smem_u32(sBh), uBl = smem_u32(sBl);

    const int tid = threadIdx.x;
    const int wid = tid >> 5, lane = tid & 31;
    const int bm = blockIdx.y * 128;
    const int bn = blockIdx.x * 128;
    const int wm = wid >> 2, wn = wid & 3;
    const int m0w = wm * 64, n0w = wn * 32;

    float acc[4][4][4];
#pragma unroll
    for (int mt = 0; mt < 4; mt++)
#pragma unroll
        for (int nt = 0; nt < 4; nt++)
#pragma unroll
            for (int e = 0; e < 4; e++) acc[mt][nt][e] = 0.f;

    const int lr = lane & 15;
    const int lc = lane >> 4;

    for (int kc = 0; kc < kchunks; kc++) {
#pragma unroll
        for (int it = 0; it < 4; it++) {
            int v = tid + it * 256;
            int r = v >> 3, c = v & 7;
            size_t gA = (size_t)(bm + r) * 384 + kc * 64 + c * 8;
            size_t gB = (size_t)(bn + r) * 384 + kc * 64 + c * 8;
            uint32_t d = r * 128 + ((c ^ (r & 7)) * 16);
            *(uint4*)(sAh + d) = *(const uint4*)(Ah + gA);
            *(uint4*)(sAl + d) = *(const uint4*)(Al + gA);
            *(uint4*)(sBh + d) = *(const uint4*)(Bh + gB);
            *(uint4*)(sBl + d) = *(const uint4*)(Bl + gB);
        }
        __syncthreads();

#pragma unroll
        for (int k16 = 0; k16 < 4; k16++) {
            const int chunk = k16 * 2 + lc;
            uint32_t aH[4][4], aL[4][4];
            uint32_t bH[4][2], bL[4][2];
#pragma unroll
            for (int mt = 0; mt < 4; mt++) {
                int r = m0w + mt * 16 + lr;
                uint32_t off = r * 128 + ((chunk ^ (r & 7)) * 16);
                ldsm_x4(aH[mt], uAh + off);
                ldsm_x4(aL[mt], uAl + off);
            }
#pragma unroll
            for (int np = 0; np < 2; np++) {
                int r = n0w + np * 16 + lr;
                uint32_t off = r * 128 + ((chunk ^ (r & 7)) * 16);
                uint32_t t[4];
                ldsm_x4(t, uBh + off);
                bH[2 * np][0] = t[0]; bH[2 * np][1] = t[2];
                bH[2 * np + 1][0] = t[1]; bH[2 * np + 1][1] = t[3];
                ldsm_x4(t, uBl + off);
                bL[2 * np][0] = t[0]; bL[2 * np][1] = t[2];
                bL[2 * np + 1][0] = t[1]; bL[2 * np + 1][1] = t[3];
            }
#pragma unroll
            for (int mt = 0; mt < 4; mt++)
#pragma unroll
                for (int nt = 0; nt < 4; nt++) {
                    mma_bf16(acc[mt][nt], aH[mt], bH[nt]);
                    mma_bf16(acc[mt][nt], aH[mt], bL[nt]);
                    mma_bf16(acc[mt][nt], aL[mt], bH[nt]);
                }
        }
        __syncthreads();
    }

    if (mode == 0) {
        // write packed bf16 hi/lo q/k/v planes
#pragma unroll
        for (int mt = 0; mt < 4; mt++) {
#pragma unroll
            for (int nt = 0; nt < 4; nt++) {
                int col = bn + n0w + nt * 8 + (lane & 3) * 2;
                int s = col / 384;
                int rem = col - s * 384;
                int hh = rem >> 5, d = rem & 31;
                float sc = (s == 0) ? QSCALE : 1.0f;
                float b0 = bias[col], b1 = bias[col + 1];
                char* plane = g_qkvp + (size_t)s * QKV_PLANE;
                int lH = d >> 3, lL = 4 + (d >> 3);
                int byt = (d & 7) * 2;
#pragma unroll
                for (int half = 0; half < 2; half++) {
                    int row = bm + m0w + mt * 16 + (lane >> 2) + half * 8;
                    int b = row / 144, i = row - b * 144;
                    float v0 = (acc[mt][nt][half * 2 + 0] + b0) * sc;
                    float v1 = (acc[mt][nt][half * 2 + 1] + b1) * sc;
                    __nv_bfloat16 h0 = __float2bfloat16(v0);
                    __nv_bfloat16 h1 = __float2bfloat16(v1);
                    uint32_t hiW = pack_bf2(h0, h1);
                    uint32_t loW = pack_bf2(__float2bfloat16(v0 - __bfloat162float(h0)),
                                            __float2bfloat16(v1 - __bfloat162float(h1)));
                    char* base = plane + ((size_t)(b * 12 + hh) * 144 + i) * 128;
                    *(uint32_t*)(base + ((lH ^ (i & 7)) * 16) + byt) = hiW;
                    *(uint32_t*)(base + ((lL ^ (i & 7)) * 16) + byt) = loW;
                }
            }
        }
    } else {
#pragma unroll
        for (int mt = 0; mt < 4; mt++) {
#pragma unroll
            for (int nt = 0; nt < 4; nt++) {
                int col = bn + n0w + nt * 8 + (lane & 3) * 2;
                float b0 = bias[col], b1 = bias[col + 1];
#pragma unroll
                for (int half = 0; half < 2; half++) {
                    int row = bm + m0w + mt * 16 + (lane >> 2) + half * 8;
                    float2 v;
                    v.x = acc[mt][nt][half * 2 + 0] + b0;
                    v.y = acc[mt][nt][half * 2 + 1] + b1;
                    *(float2*)(outp + (size_t)row * 384 + col) = v;
                }
            }
        }
    }
}

// ---------------------------------------------------------------------------
// Flash-style HMMA attention: one block per (b,h), 9 warps, warp w = m-tile w.
// Scores held in fp32 C-frags (18 n8 tiles = whole row strip), in-register
// softmax via quad shuffles, C-frags reinterpreted as PV A-frags (bf16 hi/lo).
// smem: packed Q,K,V tiles (verbatim copies, 3*18432B) + bias cache (2592 f).
// ---------------------------------------------------------------------------
__global__ __launch_bounds__(288, 1)
void attn_mma_kernel(const float* __restrict__ mask,
                     const float* __restrict__ bias_table,
                     const int*   __restrict__ pos_idx)
{
    extern __shared__ char sm[];
    char* sQ = sm;
    char* sK = sm + 18432;
    char* sV = sm + 36864;
    float* sB = (float*)(sm + 55296);
    const uint32_t uQ = smem_u32(sQ), uK = smem_u32(sK), uV = smem_u32(sV);

    const int bh = blockIdx.x;
    const int b = bh / HEADS, h = bh - b * HEADS;
    const int g  = b >> 5;
    const int t  = b & 31;
    const int mw = b & 7;

    const int tid = threadIdx.x;
    const int wid = tid >> 5, lane = tid & 31;

    // verbatim copy of packed (pre-swizzled) tiles
    {
        const uint4* q = (const uint4*)(g_qkvp + (size_t)bh * 18432);
        const uint4* k = (const uint4*)(g_qkvp + QKV_PLANE + (size_t)bh * 18432);
        const uint4* v = (const uint4*)(g_qkvp + 2 * QKV_PLANE + (size_t)bh * 18432);
        uint4* dq = (uint4*)sQ; uint4* dk = (uint4*)sK; uint4* dv = (uint4*)sV;
        for (int i = tid; i < 1152; i += 288) { dq[i] = q[i]; dk[i] = k[i]; dv[i] = v[i]; }
    }
    for (int s = tid; s < 2592; s += 288)
        sB[s] = bias_table[(size_t)pos_idx[8 * s + g] * (32 * HEADS) + t * HEADS + h];
    __syncthreads();

    const int m0 = wid * 16;
    const int gr = lane >> 2, q2 = lane & 3;
    const int i0 = m0 + gr, i1 = i0 + 8;

    // ---- init score frags with bias + mask ----
    float c[18][4];
    {
        const float* mrow0 = mask + ((size_t)mw * 144 + i0) * 144;
        const float* mrow1 = mask + ((size_t)mw * 144 + i1) * 144;
        const float* brow0 = sB + (i0 % 18) * 144;
        const float* brow1 = sB + (i1 % 18) * 144;
#pragma unroll
        for (int nt = 0; nt < 18; nt++) {
            int j = nt * 8 + q2 * 2;
            float2 mv0 = *(const float2*)(mrow0 + j);
            float2 mv1 = *(const float2*)(mrow1 + j);
            float2 bv0 = *(const float2*)(brow0 + j);
            float2 bv1 = *(const float2*)(brow1 + j);
            c[nt][0] = mv0.x + bv0.x; c[nt][1] = mv0.y + bv0.y;
            c[nt][2] = mv1.x + bv1.x; c[nt][3] = mv1.y + bv1.y;
        }
    }

    // ---- QK^T (split bf16, 3 combos) ----
    const int lr = lane & 15, lc = lane >> 4;
#pragma unroll
    for (int kk = 0; kk < 2; kk++) {
        uint32_t aH[4], aL[4];
        {
            int r = m0 + lr;
            int lH = kk * 2 + lc, lL = lH + 4;
            ldsm_x4(aH, uQ + r * 128 + ((lH ^ (r & 7)) * 16));
            ldsm_x4(aL, uQ + r * 128 + ((lL ^ (r & 7)) * 16));
        }
#pragma unroll
        for (int np = 0; np < 9; np++) {
            int r = np * 16 + lr;
            int lH = kk * 2 + lc, lL = lH + 4;
            uint32_t tH[4], tL[4];
            ldsm_x4(tH, uK + r * 128 + ((lH ^ (r & 7)) * 16));
            ldsm_x4(tL, uK + r * 128 + ((lL ^ (r & 7)) * 16));
            uint32_t b0H[2] = {tH[0], tH[2]}, b1H[2] = {tH[1], tH[3]};
            uint32_t b0L[2] = {tL[0], tL[2]}, b1L[2] = {tL[1], tL[3]};
            mma_bf16(c[2 * np],     aH, b0H);
            mma_bf16(c[2 * np],     aH, b0L);
            mma_bf16(c[2 * np],     aL, b0H);
            mma_bf16(c[2 * np + 1], aH, b1H);
            mma_bf16(c[2 * np + 1], aH, b1L);
            mma_bf16(c[2 * np + 1], aL, b1H);
        }
    }

    // ---- in-register softmax (rows live on thread quads) ----
    float mx0 = -1e30f, mx1 = -1e30f;
#pragma unroll
    for (int nt = 0; nt < 18; nt++) {
        mx0 = fmaxf(mx0, fmaxf(c[nt][0], c[nt][1]));
        mx1 = fmaxf(mx1, fmaxf(c[nt][2], c[nt][3]));
    }
    mx0 = fmaxf(mx0, __shfl_xor_sync(0xffffffffu, mx0, 1));
    mx0 = fmaxf(mx0, __shfl_xor_sync(0xffffffffu, mx0, 2));
    mx1 = fmaxf(mx1, __shfl_xor_sync(0xffffffffu, mx1, 1));
    mx1 = fmaxf(mx1, __shfl_xor_sync(0xffffffffu, mx1, 2));
    float s0 = 0.f, s1 = 0.f;
#pragma unroll
    for (int nt = 0; nt < 18; nt++) {
        c[nt][0] = __expf(c[nt][0] - mx0); s0 += c[nt][0];
        c[nt][1] = __expf(c[nt][1] - mx0); s0 += c[nt][1];
        c[nt][2] = __expf(c[nt][2] - mx1); s1 += c[nt][2];
        c[nt][3] = __expf(c[nt][3] - mx1); s1 += c[nt][3];
    }
    s0 += __shfl_xor_sync(0xffffffffu, s0, 1);
    s0 += __shfl_xor_sync(0xffffffffu, s0, 2);
    s1 += __shfl_xor_sync(0xffffffffu, s1, 1);
    s1 += __shfl_xor_sync(0xffffffffu, s1, 2);
    float inv0 = 1.f / s0, inv1 = 1.f / s1;
#pragma unroll
    for (int nt = 0; nt < 18; nt++) {
        c[nt][0] *= inv0; c[nt][1] *= inv0;
        c[nt][2] *= inv1; c[nt][3] *= inv1;
    }

    // ---- PV (P frags built from C frags; V via ldmatrix.trans) ----
    float o[4][4];
#pragma unroll
    for (int ng = 0; ng < 4; ng++)
#pragma unroll
        for (int e = 0; e < 4; e++) o[ng][e] = 0.f;

    const int grp = lane >> 3, wi = lane & 7;
#pragma unroll
    for (int kk = 0; kk < 9; kk++) {
        // A frags: hi + lo from score frags c[2kk], c[2kk+1]
        uint32_t ah[4], al[4];
#pragma unroll
        for (int p = 0; p < 4; p++) {
            const float x = c[(p < 2) ? 2 * kk : 2 * kk + 1][(p & 1) * 2 + 0];
            const float y = c[(p < 2) ? 2 * kk : 2 * kk + 1][(p & 1) * 2 + 1];
            __nv_bfloat16 hx = __float2bfloat16(x);
            __nv_bfloat16 hy = __float2bfloat16(y);
            ah[p] = pack_bf2(hx, hy);
            al[p] = pack_bf2(__float2bfloat16(x - __bfloat162float(hx)),
                             __float2bfloat16(y - __bfloat162float(hy)));
        }
        // V frags
        int r = kk * 16 + (grp & 1) * 8 + wi;
#pragma unroll
        for (int ncp = 0; ncp < 2; ncp++) {
            int lH = ncp * 2 + (grp >> 1), lL = lH + 4;
            uint32_t th[4], tl[4];
            ldsm_x4_t(th, uV + r * 128 + ((lH ^ (r & 7)) * 16));
            ldsm_x4_t(tl, uV + r * 128 + ((lL ^ (r & 7)) * 16));
            uint32_t bh0[2] = {th[0], th[1]}, bh1[2] = {th[2], th[3]};
            uint32_t bl0[2] = {tl[0], tl[1]}, bl1[2] = {tl[2], tl[3]};
            mma_bf16(o[ncp * 2],     ah, bh0);
            mma_bf16(o[ncp * 2],     ah, bl0);
            mma_bf16(o[ncp * 2],     al, bh0);
            mma_bf16(o[ncp * 2 + 1], ah, bh1);
            mma_bf16(o[ncp * 2 + 1], ah, bl1);
            mma_bf16(o[ncp * 2 + 1], al, bh1);
        }
    }

    // ---- epilogue: write split bf16 att rows ----
#pragma unroll
    for (int ng = 0; ng < 4; ng++) {
        int d = ng * 8 + q2 * 2;
        int col = h * 32 + d;
        size_t r0o = ((size_t)b * 144 + i0) * 384 + col;
        size_t r1o = ((size_t)b * 144 + i1) * 384 + col;
        __nv_bfloat16 h0 = __float2bfloat16(o[ng][0]);
        __nv_bfloat16 h1 = __float2bfloat16(o[ng][1]);
        __nv_bfloat16 h2 = __float2bfloat16(o[ng][2]);
        __nv_bfloat16 h3 = __float2bfloat16(o[ng][3]);
        *(uint32_t*)(g_att_hi + r0o) = pack_bf2(h0, h1);
        *(uint32_t*)(g_att_hi + r1o) = pack_bf2(h2, h3);
        *(uint32_t*)(g_att_lo + r0o) =
            pack_bf2(__float2bfloat16(o[ng][0] - __bfloat162float(h0)),
                     __float2bfloat16(o[ng][1] - __bfloat162float(h1)));
        *(uint32_t*)(g_att_lo + r1o) =
            pack_bf2(__float2bfloat16(o[ng][2] - __bfloat162float(h2)),
                     __float2bfloat16(o[ng][3] - __bfloat162float(h3)));
    }
}

// ---------------------------------------------------------------------------
extern "C" void kernel_launch(void* const* d_in, const int* in_sizes, int n_in,
                              void* d_out, int out_size)
{
    const float* x          = (const float*)d_in[0];
    const float* mask       = (const float*)d_in[1];
    const float* w_qkv      = (const float*)d_in[2];
    const float* b_qkv      = (const float*)d_in[3];
    const float* w_out      = (const float*)d_in[4];
    const float* b_out      = (const float*)d_in[5];
    const float* bias_table = (const float*)d_in[6];
    const int*   pos_idx    = (const int*)d_in[7];
    float* out = (float*)d_out;

    __nv_bfloat16 *xa_hi, *xa_lo, *wqT_hi, *wqT_lo, *woT_hi, *woT_lo;
    __nv_bfloat16 *att_hi, *att_lo;
    cudaGetSymbolAddress((void**)&xa_hi, g_xa_hi);
    cudaGetSymbolAddress((void**)&xa_lo, g_xa_lo);
    cudaGetSymbolAddress((void**)&wqT_hi, g_wqkvT_hi);
    cudaGetSymbolAddress((void**)&wqT_lo, g_wqkvT_lo);
    cudaGetSymbolAddress((void**)&woT_hi, g_woutT_hi);
    cudaGetSymbolAddress((void**)&woT_lo, g_woutT_lo);
    cudaGetSymbolAddress((void**)&att_hi, g_att_hi);
    cudaGetSymbolAddress((void**)&att_lo, g_att_lo);

    const int smem_gemm = 4 * TILE_B;  // 64 KB
    cudaFuncSetAttribute(hmma_gemm_kernel, cudaFuncAttributeMaxDynamicSharedMemorySize,
                         smem_gemm);
    const int smem_attn = 3 * 18432 + 2592 * 4;  // 65664
    cudaFuncSetAttribute(attn_mma_kernel, cudaFuncAttributeMaxDynamicSharedMemorySize,
                         smem_attn);

    convert_x_kernel<<<2048, 256>>>(x, xa_hi, xa_lo, MROWS * DIM / 4);
    convert_wT_kernel<<<(DIM * QKV_N + 255) / 256, 256>>>(w_qkv, wqT_hi, wqT_lo,
                                                          DIM, QKV_N);
    convert_wT_kernel<<<(DIM * DIM + 255) / 256, 256>>>(w_out, woT_hi, woT_lo,
                                                        DIM, DIM);
    // qkv projection -> packed q/k/v
    hmma_gemm_kernel<<<dim3(QKV_N / 128, MROWS / 128), 256, smem_gemm>>>(
        xa_hi, xa_lo, wqT_hi, wqT_lo, b_qkv, nullptr, 0, 6);
    // attention
    attn_mma_kernel<<<B_WIN * HEADS, 288, smem_attn>>>(mask, bias_table, pos_idx);
    // output projection
    hmma_gemm_kernel<<<dim3(DIM / 128, MROWS / 128), 256, smem_gemm>>>(
        att_hi, att_lo, woT_hi, woT_lo, b_out, out, 1, 6);
}